// round 7
// baseline (speedup 1.0000x reference)
#include <cuda_runtime.h>
#include <cstdint>

#define SEQ 512
#define BATCH 32
#define INP 1024
#define HID 1024
#define G4 4096
#define NLAYERS 4

typedef unsigned long long ull;

// ---------------- scratch (device globals; no cudaMalloc allowed) ----------------
__device__ float g_xg[(size_t)SEQ * BATCH * G4];      // x_gates for current layer
__device__ float g_buf0[(size_t)SEQ * BATCH * HID];   // layer output ping
__device__ float g_buf1[(size_t)SEQ * BATCH * HID];   // layer output pong
__device__ unsigned g_cnt[SEQ];                       // per-step arrival counters (reset by GEMM)

// ---------------- packed fp32 helpers ----------------
__device__ __forceinline__ ull ffma2(ull a, ull b, ull c) {
    ull d;
    asm("fma.rn.f32x2 %0, %1, %2, %3;" : "=l"(d) : "l"(a), "l"(b), "l"(c));
    return d;
}
__device__ __forceinline__ float hsum2(ull a) {
    float2 f;
    asm("mov.b64 {%0, %1}, %2;" : "=f"(f.x), "=f"(f.y) : "l"(a));
    return f.x + f.y;
}
__device__ __forceinline__ void cpasync16(void* dst, const void* src) {
    unsigned s = (unsigned)__cvta_generic_to_shared(dst);
    asm volatile("cp.async.cg.shared.global [%0], [%1], 16;\n" :: "r"(s), "l"(src));
}

// ---------------- input-projection GEMM (R3-proven) ----------------
#define GP 34   // smem pitch (floats): bank = (2*row + k) % 32 -> conflict-free
__global__ __launch_bounds__(256) void gemm_input_kernel(
    const float* __restrict__ Xext, int xsel,
    const float* __restrict__ W,
    const float* __restrict__ bih,
    const float* __restrict__ bhh)
{
    // reset recurrence counters for the upcoming rec launch (stream-ordered)
    if (blockIdx.x == 0 && blockIdx.y == 0)
        for (int u = threadIdx.x; u < SEQ; u += 256) g_cnt[u] = 0u;

    const float* __restrict__ X = (xsel == 0) ? Xext : (xsel == 1 ? g_buf0 : g_buf1);
    __shared__ float As[64 * GP];
    __shared__ float Bs[64 * GP];
    const int tid = threadIdx.x;
    const int tx = tid & 15, ty = tid >> 4;
    const int mB = blockIdx.y << 6;
    const int nB = blockIdx.x << 6;

    ull acc[4][4];
    #pragma unroll
    for (int i = 0; i < 4; i++)
        #pragma unroll
        for (int j = 0; j < 4; j++) acc[i][j] = 0ull;

    for (int kc = 0; kc < INP; kc += 32) {
        for (int u = tid; u < 512; u += 256) {
            int row = u >> 3, seg = (u & 7) << 2;
            float4 v = *(const float4*)&X[(size_t)(mB + row) * INP + kc + seg];
            float* p = As + row * GP + seg;
            p[0] = v.x; p[1] = v.y; p[2] = v.z; p[3] = v.w;
            float4 w = *(const float4*)&W[(size_t)(nB + row) * INP + kc + seg];
            float* q = Bs + row * GP + seg;
            q[0] = w.x; q[1] = w.y; q[2] = w.z; q[3] = w.w;
        }
        __syncthreads();
        #pragma unroll
        for (int kp = 0; kp < 16; kp++) {
            ull a[4], b[4];
            #pragma unroll
            for (int i = 0; i < 4; i++)
                a[i] = *(const ull*)&As[(ty + 16 * i) * GP + 2 * kp];
            #pragma unroll
            for (int j = 0; j < 4; j++)
                b[j] = *(const ull*)&Bs[(tx + 16 * j) * GP + 2 * kp];
            #pragma unroll
            for (int i = 0; i < 4; i++)
                #pragma unroll
                for (int j = 0; j < 4; j++)
                    acc[i][j] = ffma2(a[i], b[j], acc[i][j]);
        }
        __syncthreads();
    }

    float bsum[4];
    #pragma unroll
    for (int j = 0; j < 4; j++) {
        int n = nB + tx + 16 * j;
        bsum[j] = bih[n] + bhh[n];
    }
    #pragma unroll
    for (int i = 0; i < 4; i++) {
        size_t m = (size_t)(mB + ty + 16 * i);
        #pragma unroll
        for (int j = 0; j < 4; j++) {
            int n = nB + tx + 16 * j;
            g_xg[m * G4 + n] = hsum2(acc[i][j]) + bsum[j];
        }
    }
}

// =======================================================================
// Persistent recurrence kernel (v2: 4x4 tile, k-split 4, XOR-swizzle banks)
// 128 CTAs; CTA cb owns h-cols [cb*8, cb*8+8) => 32 gate rows.
// Threads: ks = tid>>6 (k quarter); p = tid&63: rq = p&7 (rows 4rq..+3),
// bq = p>>3 (batches 4bq..+3).  W resident in smem (swizzled, pitch 1024);
// h double-buffered in 256-k chunks (swizzled, pitch 256).
// Swizzle: element (r, k4) at column k4 ^ ((r>>2)&7)  -> stride-4-row LDS.128
// hits 8 distinct 4-bank groups. Power-of-2 pitch keeps XOR in-row.
// =======================================================================
#define REDP 20
#define REC_SMEM_FLOATS (32 * 1024 + 2 * 32 * 256 + 256 * REDP + 32 * 36 + 256)

__global__ __launch_bounds__(256) void lstm_rec_kernel(
    const float* __restrict__ Whh,    // [4096, 1024] (layer slice)
    int ysel, float* __restrict__ ysext,
    float* __restrict__ hout, float* __restrict__ cout)
{
    float* ys = (ysel == 0) ? g_buf0 : (ysel == 1 ? g_buf1 : ysext);
    extern __shared__ float sm[];
    float* ws  = sm;                    // [32][1024] swizzled
    float* hs  = ws + 32 * 1024;        // [2][32][256] swizzled
    float* red = hs + 2 * 32 * 256;     // [256][REDP]
    float* Gs  = red + 256 * REDP;      // [32][36]
    float* cs  = Gs + 32 * 36;          // [256]

    const int tid = threadIdx.x;
    const int ks  = tid >> 6;
    const int p   = tid & 63;
    const int rq  = p & 7;
    const int bq  = p >> 3;
    const int e   = rq ^ bq;
    const int c0  = blockIdx.x << 3;
    const int ab  = tid >> 3, aj = tid & 7;   // activation mapping

    // ---- load + swizzle W slice into smem once ----
    for (int u = tid; u < 8192; u += 256) {
        int r = u >> 8, k4 = u & 255;
        int grow = ((r >> 3) << 10) + c0 + (r & 7);
        int col4 = k4 ^ ((r >> 2) & 7);
        *(float4*)&ws[(r << 10) + (col4 << 2)] =
            *(const float4*)&Whh[(size_t)grow * HID + (k4 << 2)];
    }
    cs[tid] = 0.f;
    __syncthreads();

    // per-thread byte bases
    const char* wsb = (const char*)ws + ((size_t)(rq << 2) << 12);  // row 4rq, pitch 4096B

    for (int t = 0; t < SEQ; t++) {
        // prefetch this step's x_gates early (independent of h)
        const float* xgp = g_xg + ((size_t)t * BATCH + ab) * G4 + c0 + aj;
        float xgi = xgp[0], xgf = xgp[1024], xgg = xgp[2048], xgo = xgp[3072];

        ull acc[16];
        #pragma unroll
        for (int i = 0; i < 16; i++) acc[i] = 0ull;

        if (t > 0) {
            if (tid == 0) {
                volatile unsigned* fp = &g_cnt[t - 1];
                while (*fp < 128u) { __nanosleep(20); }
                __threadfence();
            }
            __syncthreads();
            const float* hsrc = ys + (size_t)(t - 1) * BATCH * HID;

            // prefetch chunk 0 (k 0..255), swizzled on b
            for (int u = tid; u < 2048; u += 256) {
                int b = u >> 6, kk4 = u & 63;
                int col4 = kk4 ^ ((b >> 2) & 7);
                cpasync16(&hs[(b << 8) + (col4 << 2)],
                          hsrc + (size_t)b * HID + (kk4 << 2));
            }
            asm volatile("cp.async.commit_group;\n");

            for (int c = 0; c < 4; c++) {
                asm volatile("cp.async.wait_group 0;\n");
                __syncthreads();           // chunk c in for all; all done computing c-1
                if (c < 3) {               // prefetch c+1 into the other buffer
                    int boff = ((c + 1) & 1) << 13;
                    for (int u = tid; u < 2048; u += 256) {
                        int b = u >> 6, kk4 = u & 63;
                        int col4 = kk4 ^ ((b >> 2) & 7);
                        cpasync16(&hs[boff + (b << 8) + (col4 << 2)],
                                  hsrc + (size_t)b * HID + ((c + 1) << 8) + (kk4 << 2));
                    }
                    asm volatile("cp.async.commit_group;\n");
                }

                const char* wb = wsb + (((c << 6) + (ks << 4)) << 4);
                const char* hb = (const char*)hs + ((c & 1) << 15)
                               + ((size_t)(bq << 2) << 10) + (ks << 8);
                #pragma unroll
                for (int pq = 0; pq < 16; pq++) {
                    int ho = (pq ^ e) << 4;
                    ulonglong2 w0 = *(const ulonglong2*)(wb + pq * 16);
                    ulonglong2 w1 = *(const ulonglong2*)(wb + 4096 + pq * 16);
                    ulonglong2 w2 = *(const ulonglong2*)(wb + 8192 + pq * 16);
                    ulonglong2 w3 = *(const ulonglong2*)(wb + 12288 + pq * 16);
                    ulonglong2 h0 = *(const ulonglong2*)(hb + ho);
                    ulonglong2 h1 = *(const ulonglong2*)(hb + 1024 + ho);
                    ulonglong2 h2 = *(const ulonglong2*)(hb + 2048 + ho);
                    ulonglong2 h3 = *(const ulonglong2*)(hb + 3072 + ho);
                    acc[0]  = ffma2(w0.x, h0.x, acc[0]);  acc[0]  = ffma2(w0.y, h0.y, acc[0]);
                    acc[1]  = ffma2(w0.x, h1.x, acc[1]);  acc[1]  = ffma2(w0.y, h1.y, acc[1]);
                    acc[2]  = ffma2(w0.x, h2.x, acc[2]);  acc[2]  = ffma2(w0.y, h2.y, acc[2]);
                    acc[3]  = ffma2(w0.x, h3.x, acc[3]);  acc[3]  = ffma2(w0.y, h3.y, acc[3]);
                    acc[4]  = ffma2(w1.x, h0.x, acc[4]);  acc[4]  = ffma2(w1.y, h0.y, acc[4]);
                    acc[5]  = ffma2(w1.x, h1.x, acc[5]);  acc[5]  = ffma2(w1.y, h1.y, acc[5]);
                    acc[6]  = ffma2(w1.x, h2.x, acc[6]);  acc[6]  = ffma2(w1.y, h2.y, acc[6]);
                    acc[7]  = ffma2(w1.x, h3.x, acc[7]);  acc[7]  = ffma2(w1.y, h3.y, acc[7]);
                    acc[8]  = ffma2(w2.x, h0.x, acc[8]);  acc[8]  = ffma2(w2.y, h0.y, acc[8]);
                    acc[9]  = ffma2(w2.x, h1.x, acc[9]);  acc[9]  = ffma2(w2.y, h1.y, acc[9]);
                    acc[10] = ffma2(w2.x, h2.x, acc[10]); acc[10] = ffma2(w2.y, h2.y, acc[10]);
                    acc[11] = ffma2(w2.x, h3.x, acc[11]); acc[11] = ffma2(w2.y, h3.y, acc[11]);
                    acc[12] = ffma2(w3.x, h0.x, acc[12]); acc[12] = ffma2(w3.y, h0.y, acc[12]);
                    acc[13] = ffma2(w3.x, h1.x, acc[13]); acc[13] = ffma2(w3.y, h1.y, acc[13]);
                    acc[14] = ffma2(w3.x, h2.x, acc[14]); acc[14] = ffma2(w3.y, h2.y, acc[14]);
                    acc[15] = ffma2(w3.x, h3.x, acc[15]); acc[15] = ffma2(w3.y, h3.y, acc[15]);
                }
            }
        } else {
            __syncthreads();
        }

        // ---- per-thread partials -> red[tid][16] (pitch 20, conflict-free STS.128) ----
        {
            float r16[16];
            #pragma unroll
            for (int i = 0; i < 16; i++) r16[i] = hsum2(acc[i]);
            #pragma unroll
            for (int v = 0; v < 4; v++)
                *(float4*)&red[tid * REDP + (v << 2)] = *(float4*)&r16[v << 2];
        }
        __syncthreads();

        // ---- k-split-4 reduction -> Gs[row][batch] (pitch 36) ----
        {
            const int pp = tid >> 2, isub = tid & 3;
            const int jb = isub << 2;
            float4 s0 = *(const float4*)&red[(0 * 64 + pp) * REDP + jb];
            float4 s1 = *(const float4*)&red[(1 * 64 + pp) * REDP + jb];
            float4 s2 = *(const float4*)&red[(2 * 64 + pp) * REDP + jb];
            float4 s3 = *(const float4*)&red[(3 * 64 + pp) * REDP + jb];
            float4 s;
            s.x = (s0.x + s1.x) + (s2.x + s3.x);
            s.y = (s0.y + s1.y) + (s2.y + s3.y);
            s.z = (s0.z + s1.z) + (s2.z + s3.z);
            s.w = (s0.w + s1.w) + (s2.w + s3.w);
            int row = ((pp & 7) << 2) + isub;
            int b0  = (pp >> 3) << 2;
            *(float4*)&Gs[row * 36 + b0] = s;
        }
        __syncthreads();

        // ---- activation ----
        {
            float gi = Gs[aj * 36 + ab]        + xgi;
            float gf = Gs[(8 + aj) * 36 + ab]  + xgf;
            float gg = Gs[(16 + aj) * 36 + ab] + xgg;
            float go = Gs[(24 + aj) * 36 + ab] + xgo;
            float si = 1.f / (1.f + expf(-gi));
            float sf = 1.f / (1.f + expf(-gf));
            float so = 1.f / (1.f + expf(-go));
            float tg = tanhf(gg);
            float cv = sf * cs[tid] + si * tg;
            float hv = so * tanhf(cv);
            cs[tid] = cv;
            ys[((size_t)t * BATCH + ab) * HID + c0 + aj] = hv;
            if (t == SEQ - 1) {
                hout[ab * HID + c0 + aj] = hv;
                cout[ab * HID + c0 + aj] = cv;
            }
        }
        __syncthreads();               // all ys stores done
        if (tid == 0) {
            __threadfence();
            atomicAdd(&g_cnt[t], 1u);
        }
    }
}

// ---------------- host launcher ----------------
extern "C" void kernel_launch(void* const* d_in, const int* in_sizes, int n_in,
                              void* d_out, int out_size) {
    const float* x   = (const float*)d_in[0];
    const float* Wih = (const float*)d_in[1];
    const float* Whh = (const float*)d_in[2];
    const float* bih = (const float*)d_in[3];
    const float* bhh = (const float*)d_in[4];
    float* out   = (float*)d_out;
    float* hbase = out + (size_t)SEQ * BATCH * HID;         // [L,B,H]
    float* cbase = hbase + (size_t)NLAYERS * BATCH * HID;   // [L,B,H]

    const int rec_smem = REC_SMEM_FLOATS * 4;
    cudaFuncSetAttribute(lstm_rec_kernel,
                         cudaFuncAttributeMaxDynamicSharedMemorySize, rec_smem);

    dim3 ggrid(G4 / 64, (SEQ * BATCH) / 64);
    for (int l = 0; l < NLAYERS; l++) {
        // layer IO ping-pong: l0:x->buf0, l1:buf0->buf1, l2:buf1->buf0, l3:buf0->d_out
        int xsel = (l == 0) ? 0 : ((l == 1) ? 1 : ((l == 2) ? 2 : 1));
        int ysel = (l == 0) ? 0 : ((l == 1) ? 1 : ((l == 2) ? 0 : 2));
        gemm_input_kernel<<<ggrid, 256>>>(x, xsel,
            Wih + (size_t)l * G4 * INP,
            bih + (size_t)l * G4,
            bhh + (size_t)l * G4);
        lstm_rec_kernel<<<128, 256, rec_smem>>>(Whh + (size_t)l * G4 * HID, ysel, out,
            hbase + (size_t)l * BATCH * HID,
            cbase + (size_t)l * BATCH * HID);
    }
}

// round 13
// speedup vs baseline: 1.6735x; 1.6735x over previous
#include <cuda_runtime.h>
#include <cstdint>

#define SEQ 512
#define BATCH 32
#define INP 1024
#define HID 1024
#define G4 4096
#define NLAYERS 4

typedef unsigned long long ull;

// ---------------- scratch (device globals; no cudaMalloc allowed) ----------------
__device__ float g_xg[(size_t)SEQ * BATCH * G4];      // x_gates for current layer
__device__ float g_buf0[(size_t)SEQ * BATCH * HID];   // layer output ping
__device__ float g_buf1[(size_t)SEQ * BATCH * HID];   // layer output pong
__device__ int   g_gcnt[8];                           // per-group progress counters (reset by GEMM)

// ---------------- packed fp32 helpers ----------------
__device__ __forceinline__ ull ffma2(ull a, ull b, ull c) {
    ull d;
    asm("fma.rn.f32x2 %0, %1, %2, %3;" : "=l"(d) : "l"(a), "l"(b), "l"(c));
    return d;
}
__device__ __forceinline__ float hsum2(ull a) {
    float2 f;
    asm("mov.b64 {%0, %1}, %2;" : "=f"(f.x), "=f"(f.y) : "l"(a));
    return f.x + f.y;
}
__device__ __forceinline__ void cpasync8(void* dst, const void* src) {
    unsigned s = (unsigned)__cvta_generic_to_shared(dst);
    asm volatile("cp.async.ca.shared.global [%0], [%1], 8;\n" :: "r"(s), "l"(src));
}

// ---------------- input-projection GEMM (R3-proven) ----------------
#define GP 34   // smem pitch (floats): bank = (2*row + k) % 32 -> conflict-free
__global__ __launch_bounds__(256) void gemm_input_kernel(
    const float* __restrict__ Xext, int xsel,
    const float* __restrict__ W,
    const float* __restrict__ bih,
    const float* __restrict__ bhh)
{
    // reset recurrence counters for the upcoming rec launch (stream-ordered)
    if (blockIdx.x == 0 && blockIdx.y == 0 && threadIdx.x < 8)
        g_gcnt[threadIdx.x] = 0;

    const float* __restrict__ X = (xsel == 0) ? Xext : (xsel == 1 ? g_buf0 : g_buf1);
    __shared__ float As[64 * GP];
    __shared__ float Bs[64 * GP];
    const int tid = threadIdx.x;
    const int tx = tid & 15, ty = tid >> 4;
    const int mB = blockIdx.y << 6;
    const int nB = blockIdx.x << 6;

    ull acc[4][4];
    #pragma unroll
    for (int i = 0; i < 4; i++)
        #pragma unroll
        for (int j = 0; j < 4; j++) acc[i][j] = 0ull;

    for (int kc = 0; kc < INP; kc += 32) {
        for (int u = tid; u < 512; u += 256) {
            int row = u >> 3, seg = (u & 7) << 2;
            float4 v = *(const float4*)&X[(size_t)(mB + row) * INP + kc + seg];
            float* p = As + row * GP + seg;
            p[0] = v.x; p[1] = v.y; p[2] = v.z; p[3] = v.w;
            float4 w = *(const float4*)&W[(size_t)(nB + row) * INP + kc + seg];
            float* q = Bs + row * GP + seg;
            q[0] = w.x; q[1] = w.y; q[2] = w.z; q[3] = w.w;
        }
        __syncthreads();
        #pragma unroll
        for (int kp = 0; kp < 16; kp++) {
            ull a[4], b[4];
            #pragma unroll
            for (int i = 0; i < 4; i++)
                a[i] = *(const ull*)&As[(ty + 16 * i) * GP + 2 * kp];
            #pragma unroll
            for (int j = 0; j < 4; j++)
                b[j] = *(const ull*)&Bs[(tx + 16 * j) * GP + 2 * kp];
            #pragma unroll
            for (int i = 0; i < 4; i++)
                #pragma unroll
                for (int j = 0; j < 4; j++)
                    acc[i][j] = ffma2(a[i], b[j], acc[i][j]);
        }
        __syncthreads();
    }

    float bsum[4];
    #pragma unroll
    for (int j = 0; j < 4; j++) {
        int n = nB + tx + 16 * j;
        bsum[j] = bih[n] + bhh[n];
    }
    #pragma unroll
    for (int i = 0; i < 4; i++) {
        size_t m = (size_t)(mB + ty + 16 * i);
        #pragma unroll
        for (int j = 0; j < 4; j++) {
            int n = nB + tx + 16 * j;
            g_xg[m * G4 + n] = hsum2(acc[i][j]) + bsum[j];
        }
    }
}

// =======================================================================
// Persistent recurrence kernel (v3: 256 CTAs, 2 CTAs/SM for latency hiding)
// CTA cb owns h-cols [cb*4, cb*4+4) => 16 gate rows {g*1024 + cb*4 + j, j<4}.
// Threads: tx = tid&15 (batches tx, tx+16), rp = (tid>>4)&7 (rows rp, rp+8),
// ks = tid>>7 (k half of each chunk). W (16x1024) resident in smem.
// h consumed in 8 chunks of 128 cols; chunk g produced by CTAs 32g..32g+31;
// staggered consumption order starting at own group; cp.async double buffer.
// No swizzle: h loads broadcast (bank = 2*tx distinct), w loads 2-row broadcast.
// =======================================================================
#define WPR 1028     // w pitch (floats)
#define HPR 130      // h pitch (floats): banks 2*tx distinct, 8B aligned rows
#define HBUF (32 * HPR)
#define REC_SMEM_FLOATS (16 * WPR + 2 * HBUF + 256 * 4 + 16 * 40 + 128)

__global__ __launch_bounds__(256, 2) void lstm_rec_kernel(
    const float* __restrict__ Whh,    // [4096, 1024] (layer slice)
    int ysel, float* __restrict__ ysext,
    float* __restrict__ hout, float* __restrict__ cout)
{
    float* ys = (ysel == 0) ? g_buf0 : (ysel == 1 ? g_buf1 : ysext);
    extern __shared__ float sm[];
    float* ws  = sm;                    // [16][WPR]
    float* hs  = ws + 16 * WPR;         // [2][32][HPR]
    float* red = hs + 2 * HBUF;         // [256][4]
    float* Gs  = red + 256 * 4;         // [16][40]
    float* cs  = Gs + 16 * 40;          // [128]

    const int tid = threadIdx.x;
    const int tx  = tid & 15;           // batches tx, tx+16
    const int rp  = (tid >> 4) & 7;     // rows rp, rp+8
    const int ks  = tid >> 7;           // k half within each chunk
    const int cb  = blockIdx.x;
    const int c0  = cb << 2;
    const int gp  = cb >> 5;            // producer group / first consumed chunk
    const int ab  = tid >> 2, aj = tid & 3;   // activation mapping (tid < 128)

    // ---- load W slice (16 rows x 1024) into smem once ----
    for (int u = tid; u < 4096; u += 256) {
        int r = u >> 8, s = (u & 255) << 2;
        int grow = ((r >> 2) << 10) + c0 + (r & 3);
        *(float4*)&ws[r * WPR + s] = *(const float4*)&Whh[(size_t)grow * HID + s];
    }
    if (tid < 128) cs[tid] = 0.f;
    __syncthreads();

    const float* wr0 = ws + rp * WPR;
    const float* wr1 = ws + (rp + 8) * WPR;

    for (int t = 0; t < SEQ; t++) {
        // prefetch this step's x_gates early (independent of h)
        float xgi = 0.f, xgf = 0.f, xgg = 0.f, xgo = 0.f;
        if (tid < 128) {
            const float* xgp = g_xg + ((size_t)t * BATCH + ab) * G4 + c0 + aj;
            xgi = xgp[0]; xgf = xgp[1024]; xgg = xgp[2048]; xgo = xgp[3072];
        }

        ull acc0a = 0, acc0b = 0, acc1a = 0, acc1b = 0;
        ull acc2a = 0, acc2b = 0, acc3a = 0, acc3b = 0;

        if (t > 0) {
            const float* hsrc = ys + (size_t)(t - 1) * BATCH * HID;
            const int need = t << 5;    // 32 producers per group per step

            // prologue: wait own group's chunk, prefetch into buf0
            if (tid == 0) {
                volatile int* fp = g_gcnt + gp;
                while (*fp < need) { __nanosleep(20); }
                __threadfence();
            }
            __syncthreads();
            for (int u = tid; u < 2048; u += 256) {
                int b = u >> 6, s2 = (u & 63) << 1;
                cpasync8(&hs[b * HPR + s2],
                         hsrc + (size_t)b * HID + (gp << 7) + s2);
            }
            asm volatile("cp.async.commit_group;\n");

            for (int i = 0; i < 8; i++) {
                const int gc = (gp + i) & 7;
                if (i < 7) {
                    const int gn = (gp + i + 1) & 7;
                    if (tid == 0) {
                        volatile int* fp = g_gcnt + gn;
                        while (*fp < need) { __nanosleep(20); }
                        __threadfence();
                    }
                    __syncthreads();    // release prefetch; proves compute(i-1) done
                    float* dst = hs + ((i + 1) & 1) * HBUF;
                    for (int u = tid; u < 2048; u += 256) {
                        int b = u >> 6, s2 = (u & 63) << 1;
                        cpasync8(dst + b * HPR + s2,
                                 hsrc + (size_t)b * HID + (gn << 7) + s2);
                    }
                    asm volatile("cp.async.commit_group;\n");
                    asm volatile("cp.async.wait_group 1;\n");
                } else {
                    asm volatile("cp.async.wait_group 0;\n");
                }
                __syncthreads();        // chunk i visible to all warps

                const float* hb0 = hs + (i & 1) * HBUF + tx * HPR + (ks << 6);
                const float* hb1 = hs + (i & 1) * HBUF + (tx + 16) * HPR + (ks << 6);
                const float* w0p = wr0 + (gc << 7) + (ks << 6);
                const float* w1p = wr1 + (gc << 7) + (ks << 6);
                #pragma unroll
                for (int q = 0; q < 16; q++) {
                    int k = q << 2;
                    ull h00 = *(const ull*)(hb0 + k);
                    ull h02 = *(const ull*)(hb0 + k + 2);
                    ull h10 = *(const ull*)(hb1 + k);
                    ull h12 = *(const ull*)(hb1 + k + 2);
                    ulonglong2 w0 = *(const ulonglong2*)(w0p + k);
                    ulonglong2 w1 = *(const ulonglong2*)(w1p + k);
                    acc0a = ffma2(h00, w0.x, acc0a);
                    acc0b = ffma2(h02, w0.y, acc0b);
                    acc1a = ffma2(h10, w0.x, acc1a);
                    acc1b = ffma2(h12, w0.y, acc1b);
                    acc2a = ffma2(h00, w1.x, acc2a);
                    acc2b = ffma2(h02, w1.y, acc2b);
                    acc3a = ffma2(h10, w1.x, acc3a);
                    acc3b = ffma2(h12, w1.y, acc3b);
                }
            }
        } else {
            __syncthreads();
        }

        // ---- per-thread partials (k-half) -> red[tid][4] ----
        {
            float4 pv;
            pv.x = hsum2(acc0a) + hsum2(acc0b);   // (row rp,   b tx)
            pv.y = hsum2(acc1a) + hsum2(acc1b);   // (row rp,   b tx+16)
            pv.z = hsum2(acc2a) + hsum2(acc2b);   // (row rp+8, b tx)
            pv.w = hsum2(acc3a) + hsum2(acc3b);   // (row rp+8, b tx+16)
            *(float4*)&red[tid << 2] = pv;
        }
        __syncthreads();

        // ---- k-split-2 reduction -> Gs[row][batch] (pitch 40) ----
        if (tid < 128) {
            float4 u0 = *(const float4*)&red[tid << 2];
            float4 u1 = *(const float4*)&red[(tid + 128) << 2];
            int rr = tid >> 4;      // 0..7
            int bb = tid & 15;
            Gs[rr * 40 + bb]             = u0.x + u1.x;
            Gs[rr * 40 + bb + 16]        = u0.y + u1.y;
            Gs[(rr + 8) * 40 + bb]       = u0.z + u1.z;
            Gs[(rr + 8) * 40 + bb + 16]  = u0.w + u1.w;
        }
        __syncthreads();

        // ---- activation: 128 threads, one (batch, col) each ----
        if (tid < 128) {
            float gi = Gs[aj * 40 + ab]        + xgi;
            float gf = Gs[(4 + aj) * 40 + ab]  + xgf;
            float gg = Gs[(8 + aj) * 40 + ab]  + xgg;
            float go = Gs[(12 + aj) * 40 + ab] + xgo;
            float si = 1.f / (1.f + expf(-gi));
            float sf = 1.f / (1.f + expf(-gf));
            float so = 1.f / (1.f + expf(-go));
            float tg = tanhf(gg);
            float cv = sf * cs[tid] + si * tg;
            float hv = so * tanhf(cv);
            cs[tid] = cv;
            ys[((size_t)t * BATCH + ab) * HID + c0 + aj] = hv;
            if (t == SEQ - 1) {
                hout[ab * HID + c0 + aj] = hv;
                cout[ab * HID + c0 + aj] = cv;
            }
        }
        __syncthreads();                // all ys stores done
        if (tid == 0) {
            __threadfence();
            atomicAdd(&g_gcnt[gp], 1);
        }
    }
}

// ---------------- host launcher ----------------
extern "C" void kernel_launch(void* const* d_in, const int* in_sizes, int n_in,
                              void* d_out, int out_size) {
    const float* x   = (const float*)d_in[0];
    const float* Wih = (const float*)d_in[1];
    const float* Whh = (const float*)d_in[2];
    const float* bih = (const float*)d_in[3];
    const float* bhh = (const float*)d_in[4];
    float* out   = (float*)d_out;
    float* hbase = out + (size_t)SEQ * BATCH * HID;         // [L,B,H]
    float* cbase = hbase + (size_t)NLAYERS * BATCH * HID;   // [L,B,H]

    const int rec_smem = REC_SMEM_FLOATS * 4;
    cudaFuncSetAttribute(lstm_rec_kernel,
                         cudaFuncAttributeMaxDynamicSharedMemorySize, rec_smem);

    dim3 ggrid(G4 / 64, (SEQ * BATCH) / 64);
    for (int l = 0; l < NLAYERS; l++) {
        // layer IO ping-pong: l0:x->buf0, l1:buf0->buf1, l2:buf1->buf0, l3:buf0->d_out
        int xsel = (l == 0) ? 0 : ((l == 1) ? 1 : ((l == 2) ? 2 : 1));
        int ysel = (l == 0) ? 0 : ((l == 1) ? 1 : ((l == 2) ? 0 : 2));
        gemm_input_kernel<<<ggrid, 256>>>(x, xsel,
            Wih + (size_t)l * G4 * INP,
            bih + (size_t)l * G4,
            bhh + (size_t)l * G4);
        lstm_rec_kernel<<<256, 256, rec_smem>>>(Whh + (size_t)l * G4 * HID, ysel, out,
            hbase + (size_t)l * BATCH * HID,
            cbase + (size_t)l * BATCH * HID);
    }
}

// round 14
// speedup vs baseline: 3.1097x; 1.8582x over previous
#include <cuda_runtime.h>
#include <cuda_bf16.h>
#include <cstdint>

#define SEQ 512
#define BATCH 32
#define INP 1024
#define HID 1024
#define G4 4096
#define NLAYERS 4

typedef unsigned long long ull;

// ---------------- scratch (device globals; no cudaMalloc allowed) ----------------
__device__ float g_xg[(size_t)SEQ * BATCH * G4];          // x_gates for current layer
__device__ float g_buf0[(size_t)SEQ * BATCH * HID];       // layer output ping (fp32)
__device__ float g_buf1[(size_t)SEQ * BATCH * HID];       // layer output pong (fp32)
__device__ __nv_bfloat16 g_yhi[(size_t)SEQ * BATCH * HID];  // h bf16 hi, [t][b][k] swizzled
__device__ __nv_bfloat16 g_ylo[(size_t)SEQ * BATCH * HID];  // h bf16 lo
__device__ unsigned g_cnt[SEQ];                           // per-step arrival counters (reset by GEMM)

// ---------------- packed fp32 helpers (GEMM) ----------------
__device__ __forceinline__ ull ffma2(ull a, ull b, ull c) {
    ull d;
    asm("fma.rn.f32x2 %0, %1, %2, %3;" : "=l"(d) : "l"(a), "l"(b), "l"(c));
    return d;
}
__device__ __forceinline__ float hsum2(ull a) {
    float2 f;
    asm("mov.b64 {%0, %1}, %2;" : "=f"(f.x), "=f"(f.y) : "l"(a));
    return f.x + f.y;
}
__device__ __forceinline__ void cpasync16(void* dst, const void* src) {
    unsigned s = (unsigned)__cvta_generic_to_shared(dst);
    asm volatile("cp.async.ca.shared.global [%0], [%1], 16;\n" :: "r"(s), "l"(src));
}

// ---------------- mma helpers ----------------
__device__ __forceinline__ void ldsm_x4(uint32_t& r0, uint32_t& r1, uint32_t& r2, uint32_t& r3,
                                        uint32_t addr) {
    asm volatile("ldmatrix.sync.aligned.m8n8.x4.shared.b16 {%0,%1,%2,%3}, [%4];"
                 : "=r"(r0), "=r"(r1), "=r"(r2), "=r"(r3) : "r"(addr));
}
__device__ __forceinline__ void ldsm_x2(uint32_t& r0, uint32_t& r1, uint32_t addr) {
    asm volatile("ldmatrix.sync.aligned.m8n8.x2.shared.b16 {%0,%1}, [%2];"
                 : "=r"(r0), "=r"(r1) : "r"(addr));
}
__device__ __forceinline__ void mma16816(float* c, const uint32_t* a, const uint32_t* b) {
    asm volatile("mma.sync.aligned.m16n8k16.row.col.f32.bf16.bf16.f32 "
                 "{%0,%1,%2,%3}, {%4,%5,%6,%7}, {%8,%9}, {%0,%1,%2,%3};"
                 : "+f"(c[0]), "+f"(c[1]), "+f"(c[2]), "+f"(c[3])
                 : "r"(a[0]), "r"(a[1]), "r"(a[2]), "r"(a[3]), "r"(b[0]), "r"(b[1]));
}

// ---------------- input-projection GEMM (R3-proven) ----------------
#define GP 34   // smem pitch (floats): bank = (2*row + k) % 32 -> conflict-free
__global__ __launch_bounds__(256) void gemm_input_kernel(
    const float* __restrict__ Xext, int xsel,
    const float* __restrict__ W,
    const float* __restrict__ bih,
    const float* __restrict__ bhh)
{
    // reset recurrence counters for the upcoming rec launch (stream-ordered)
    if (blockIdx.x == 0 && blockIdx.y == 0)
        for (int u = threadIdx.x; u < SEQ; u += 256) g_cnt[u] = 0u;

    const float* __restrict__ X = (xsel == 0) ? Xext : (xsel == 1 ? g_buf0 : g_buf1);
    __shared__ float As[64 * GP];
    __shared__ float Bs[64 * GP];
    const int tid = threadIdx.x;
    const int tx = tid & 15, ty = tid >> 4;
    const int mB = blockIdx.y << 6;
    const int nB = blockIdx.x << 6;

    ull acc[4][4];
    #pragma unroll
    for (int i = 0; i < 4; i++)
        #pragma unroll
        for (int j = 0; j < 4; j++) acc[i][j] = 0ull;

    for (int kc = 0; kc < INP; kc += 32) {
        for (int u = tid; u < 512; u += 256) {
            int row = u >> 3, seg = (u & 7) << 2;
            float4 v = *(const float4*)&X[(size_t)(mB + row) * INP + kc + seg];
            float* p = As + row * GP + seg;
            p[0] = v.x; p[1] = v.y; p[2] = v.z; p[3] = v.w;
            float4 w = *(const float4*)&W[(size_t)(nB + row) * INP + kc + seg];
            float* q = Bs + row * GP + seg;
            q[0] = w.x; q[1] = w.y; q[2] = w.z; q[3] = w.w;
        }
        __syncthreads();
        #pragma unroll
        for (int kp = 0; kp < 16; kp++) {
            ull a[4], b[4];
            #pragma unroll
            for (int i = 0; i < 4; i++)
                a[i] = *(const ull*)&As[(ty + 16 * i) * GP + 2 * kp];
            #pragma unroll
            for (int j = 0; j < 4; j++)
                b[j] = *(const ull*)&Bs[(tx + 16 * j) * GP + 2 * kp];
            #pragma unroll
            for (int i = 0; i < 4; i++)
                #pragma unroll
                for (int j = 0; j < 4; j++)
                    acc[i][j] = ffma2(a[i], b[j], acc[i][j]);
        }
        __syncthreads();
    }

    float bsum[4];
    #pragma unroll
    for (int j = 0; j < 4; j++) {
        int n = nB + tx + 16 * j;
        bsum[j] = bih[n] + bhh[n];
    }
    #pragma unroll
    for (int i = 0; i < 4; i++) {
        size_t m = (size_t)(mB + ty + 16 * i);
        #pragma unroll
        for (int j = 0; j < 4; j++) {
            int n = nB + tx + 16 * j;
            g_xg[m * G4 + n] = hsum2(acc[i][j]) + bsum[j];
        }
    }
}

// =======================================================================
// Persistent recurrence kernel (v4: bf16-split HMMA)
// 128 CTAs; CTA cb owns h-cols [cb*8, cb*8+8) => 32 gate rows (r>>3=gate, r&7=col).
// Per step: D[32r x 32b] = Wslice[32x1024] @ h[1024x32] via mma.m16n8k16 bf16,
// 3 split products (hh, hl, lh) with fp32 accum.
// W bf16 hi/lo resident in smem (XOR-swizzled for ldmatrix); h bf16 hi/lo read
// from global (produced swizzled by prior step) in 4 chunks of 256 k, cp.async
// double-buffered. 8 warps = 2(M) x 4(N) tiles, no cross-warp reduction.
// =======================================================================
#define S_AHI 0
#define S_ALO 65536
#define S_HS  131072         // [buf][hi 16K | lo 16K], buf stride 32768
#define S_GS  196608         // float[32][36]
#define S_CS  201216         // float[256]
#define REC_SMEM_BYTES 202240

__global__ __launch_bounds__(256) void lstm_rec_kernel(
    const float* __restrict__ Whh,    // [4096, 1024] (layer slice)
    int ysel, float* __restrict__ ysext,
    float* __restrict__ hout, float* __restrict__ cout)
{
    float* ys = (ysel == 0) ? g_buf0 : (ysel == 1 ? g_buf1 : ysext);
    extern __shared__ char smc[];
    float* Gs = (float*)(smc + S_GS);
    float* cs = (float*)(smc + S_CS);
    const uint32_t smb = (uint32_t)__cvta_generic_to_shared(smc);

    const int tid  = threadIdx.x;
    const int lane = tid & 31;
    const int warp = tid >> 5;
    const int mw   = warp & 1;          // M half (16 rows)
    const int nw   = warp >> 1;         // N quarter (8 batches)
    const int cb   = blockIdx.x;
    const int c0   = cb << 3;
    const int ab   = tid >> 3, aj = tid & 7;   // activation mapping

    // A-frag lane addressing (tiles: r0-7/k0, r8-15/k0, r0-7/k1, r8-15/k1)
    const int tileid = lane >> 3;
    const int arow   = 16 * mw + 8 * (tileid & 1) + (lane & 7);
    const int ahalf  = tileid >> 1;
    const int amask  = arow & 7;
    // B-frag lane addressing (x2: lanes 0-15; tiles: n/k0, n/k1)
    const int bhalf  = (lane >> 3) & 1;
    const int brow   = 8 * nw + (lane & 7);
    const int bmask  = brow & 7;

    // ---- convert W slice (32x1024 fp32) -> smem bf16 hi/lo, swizzled ----
    for (int u = tid; u < 4096; u += 256) {            // u = row*128 + seg
        int r = u >> 7, s = u & 127;
        int grow = ((r >> 3) << 10) + c0 + (r & 7);
        const float* wp = Whh + (size_t)grow * HID + (s << 3);
        float4 v0 = *(const float4*)wp;
        float4 v1 = *(const float4*)(wp + 4);
        float w8[8] = {v0.x, v0.y, v0.z, v0.w, v1.x, v1.y, v1.z, v1.w};
        __nv_bfloat16 hi[8], lo[8];
        #pragma unroll
        for (int e = 0; e < 8; e++) {
            hi[e] = __float2bfloat16_rn(w8[e]);
            lo[e] = __float2bfloat16_rn(w8[e] - __bfloat162float(hi[e]));
        }
        int p = s ^ (r & 7);
        *(uint4*)(smc + S_AHI + r * 2048 + p * 16) = *(uint4*)hi;
        *(uint4*)(smc + S_ALO + r * 2048 + p * 16) = *(uint4*)lo;
    }
    cs[tid] = 0.f;
    __syncthreads();

    for (int t = 0; t < SEQ; t++) {
        // prefetch this step's x_gates early (independent of h)
        const float* xgp = g_xg + ((size_t)t * BATCH + ab) * G4 + c0 + aj;
        float xgi = xgp[0], xgf = xgp[1024], xgg = xgp[2048], xgo = xgp[3072];

        float chh[4] = {0.f, 0.f, 0.f, 0.f};
        float chl[4] = {0.f, 0.f, 0.f, 0.f};
        float clh[4] = {0.f, 0.f, 0.f, 0.f};

        if (t > 0) {
            if (tid == 0) {
                volatile unsigned* fp = &g_cnt[t - 1];
                while (*fp < 128u) { __nanosleep(20); }
                __threadfence();
            }
            __syncthreads();
            const char* hihome = (const char*)g_yhi + ((size_t)(t - 1) * BATCH) * HID * 2;
            const char* lohome = (const char*)g_ylo + ((size_t)(t - 1) * BATCH) * HID * 2;

            // prefetch chunk 0: positions [0,32) of each batch row (hi+lo)
            for (int u = tid; u < 2048; u += 256) {    // u = half*1024 + b*32 + sl
                int half = u >> 10, v = u & 1023, b = v >> 5, sl = v & 31;
                const char* src = (half ? lohome : hihome) + b * 2048 + sl * 16;
                cpasync16(smc + S_HS + half * 16384 + b * 512 + sl * 16, src);
            }
            asm volatile("cp.async.commit_group;\n");

            for (int c = 0; c < 4; c++) {
                asm volatile("cp.async.wait_group 0;\n");
                __syncthreads();       // chunk c ready for all; all done computing c-1
                if (c < 3) {           // prefetch c+1 into other buffer (c-1's, now free)
                    int boff = ((c + 1) & 1) * 32768;
                    for (int u = tid; u < 2048; u += 256) {
                        int half = u >> 10, v = u & 1023, b = v >> 5, sl = v & 31;
                        const char* src = (half ? lohome : hihome)
                                        + b * 2048 + ((c + 1) * 32 + sl) * 16;
                        cpasync16(smc + S_HS + boff + half * 16384 + b * 512 + sl * 16, src);
                    }
                    asm volatile("cp.async.commit_group;\n");
                }

                const uint32_t hsb = smb + S_HS + ((c & 1) ? 32768u : 0u);
                const uint32_t abase = smb + S_AHI + arow * 2048;
                const uint32_t bbase = hsb + brow * 512;
                #pragma unroll 8
                for (int t16 = 0; t16 < 16; t16++) {
                    int sA = (c << 5) + (t16 << 1) + ahalf;
                    uint32_t aaddr = abase + (uint32_t)((sA ^ amask) << 4);
                    uint32_t ahi[4], alo[4];
                    ldsm_x4(ahi[0], ahi[1], ahi[2], ahi[3], aaddr);
                    ldsm_x4(alo[0], alo[1], alo[2], alo[3], aaddr + 65536);
                    int sB = (t16 << 1) + bhalf;
                    uint32_t baddr = bbase + (uint32_t)((sB ^ bmask) << 4);
                    uint32_t bhi[2], blo[2];
                    ldsm_x2(bhi[0], bhi[1], baddr);
                    ldsm_x2(blo[0], blo[1], baddr + 16384);
                    mma16816(chh, ahi, bhi);
                    mma16816(chl, ahi, blo);
                    mma16816(clh, alo, bhi);
                }
            }
        } else {
            __syncthreads();
        }

        // ---- epilogue: frag accumulators -> Gs[row][batch] (pitch 36) ----
        {
            int r = 16 * mw + (lane >> 2);
            int b = 8 * nw + ((lane & 3) << 1);
            float2 lo2, hi2;
            lo2.x = chh[0] + chl[0] + clh[0];
            lo2.y = chh[1] + chl[1] + clh[1];
            hi2.x = chh[2] + chl[2] + clh[2];
            hi2.y = chh[3] + chl[3] + clh[3];
            *(float2*)&Gs[r * 36 + b]       = lo2;
            *(float2*)&Gs[(r + 8) * 36 + b] = hi2;
        }
        __syncthreads();

        // ---- activation: thread (ab, aj) ----
        {
            float gi = Gs[aj * 36 + ab]        + xgi;
            float gf = Gs[(8 + aj) * 36 + ab]  + xgf;
            float gg = Gs[(16 + aj) * 36 + ab] + xgg;
            float go = Gs[(24 + aj) * 36 + ab] + xgo;
            float si = 1.f / (1.f + expf(-gi));
            float sf = 1.f / (1.f + expf(-gf));
            float so = 1.f / (1.f + expf(-go));
            float tg = tanhf(gg);
            float cv = sf * cs[tid] + si * tg;
            float hv = so * tanhf(cv);
            cs[tid] = cv;
            ys[((size_t)t * BATCH + ab) * HID + c0 + aj] = hv;
            // bf16 split, swizzled [b][k] layout: k = cb*8 + aj -> seg cb, elem aj
            __nv_bfloat16 hhi = __float2bfloat16_rn(hv);
            __nv_bfloat16 hlo = __float2bfloat16_rn(hv - __bfloat162float(hhi));
            size_t hoff = ((size_t)t * BATCH + ab) * HID + ((cb ^ (ab & 7)) << 3) + aj;
            g_yhi[hoff] = hhi;
            g_ylo[hoff] = hlo;
            if (t == SEQ - 1) {
                hout[ab * HID + c0 + aj] = hv;
                cout[ab * HID + c0 + aj] = cv;
            }
        }
        __syncthreads();               // all h stores done
        if (tid == 0) {
            __threadfence();
            atomicAdd(&g_cnt[t], 1u);
        }
    }
}

// ---------------- host launcher ----------------
extern "C" void kernel_launch(void* const* d_in, const int* in_sizes, int n_in,
                              void* d_out, int out_size) {
    const float* x   = (const float*)d_in[0];
    const float* Wih = (const float*)d_in[1];
    const float* Whh = (const float*)d_in[2];
    const float* bih = (const float*)d_in[3];
    const float* bhh = (const float*)d_in[4];
    float* out   = (float*)d_out;
    float* hbase = out + (size_t)SEQ * BATCH * HID;         // [L,B,H]
    float* cbase = hbase + (size_t)NLAYERS * BATCH * HID;   // [L,B,H]

    cudaFuncSetAttribute(lstm_rec_kernel,
                         cudaFuncAttributeMaxDynamicSharedMemorySize, REC_SMEM_BYTES);

    dim3 ggrid(G4 / 64, (SEQ * BATCH) / 64);
    for (int l = 0; l < NLAYERS; l++) {
        // layer IO ping-pong: l0:x->buf0, l1:buf0->buf1, l2:buf1->buf0, l3:buf0->d_out
        int xsel = (l == 0) ? 0 : ((l == 1) ? 1 : ((l == 2) ? 2 : 1));
        int ysel = (l == 0) ? 0 : ((l == 1) ? 1 : ((l == 2) ? 0 : 2));
        gemm_input_kernel<<<ggrid, 256>>>(x, xsel,
            Wih + (size_t)l * G4 * INP,
            bih + (size_t)l * G4,
            bhh + (size_t)l * G4);
        lstm_rec_kernel<<<128, 256, REC_SMEM_BYTES>>>(Whh + (size_t)l * G4 * HID, ysel, out,
            hbase + (size_t)l * BATCH * HID,
            cbase + (size_t)l * BATCH * HID);
    }
}